// round 2
// baseline (speedup 1.0000x reference)
#include <cuda_runtime.h>

#define D   128   // LATDIM
#define A   64    // ANCHOR_SET_NUM
#define TN  64    // n-tile for main kernel

// Scratch (allocation-free rule: __device__ globals)
__device__ float g_V[A * D];        // (1/A) * set_emb @ W1^T   [A][D]
__device__ float g_C[10000 * D];    // per-window constant      [T][D] (T <= N)

// ---------------------------------------------------------------------------
// f32x2 packed-FMA helpers (sm_103a FFMA2, PTX-only)
// ---------------------------------------------------------------------------
__device__ __forceinline__ unsigned long long pk2(float x, float y) {
    unsigned long long r;
    asm("mov.b64 %0, {%1, %2};" : "=l"(r) : "f"(x), "f"(y));
    return r;
}
__device__ __forceinline__ void unpk2(unsigned long long v, float& x, float& y) {
    asm("mov.b64 {%0, %1}, %2;" : "=f"(x), "=f"(y) : "l"(v));
}
__device__ __forceinline__ void ffma2(unsigned long long& a,
                                      unsigned long long b,
                                      unsigned long long c) {
    asm("fma.rn.f32x2 %0, %1, %2, %0;" : "+l"(a) : "l"(b), "l"(c));
}

// ---------------------------------------------------------------------------
// k_pre: fused precompute of g_V and g_C. No warp shuffles.
//   grid = 2*(T + A), 128 threads.
//   block (idx, half): idx < T  -> C[idx][o0..o0+64)
//                      idx >= T -> V[idx-T][o0..o0+64)
//   C[t][o] = (1/A) * sum_k E2[t][k] * W[o][D+k] + b[o],
//     E2[t] = sum_{a<A} embeds[(g*t + a) mod N]
//   V[a][o] = (1/A) * sum_k embeds[anchor[a]][k] * W[o][k]
// smem: W slice staged coalesced, padded (129) for conflict-free dot reads.
// ---------------------------------------------------------------------------
__global__ __launch_bounds__(128) void k_pre(const float* __restrict__ embeds,
                                             const float* __restrict__ W,
                                             const float* __restrict__ b,
                                             const int*   __restrict__ anchor,
                                             int N, int T, int g) {
    __shared__ float w[64][129];   // ~33 KB
    __shared__ float ev[D];
    __shared__ float part[64];

    const int idx = blockIdx.x >> 1;
    const int o0  = (blockIdx.x & 1) * 64;
    const int tid = threadIdx.x;
    const bool is_const = (idx < T);
    const int woff = is_const ? D : 0;

    // stage W rows [o0, o0+64), cols [woff, woff+D) — coalesced float4 loads
    #pragma unroll
    for (int i = tid; i < 64 * 32; i += 128) {
        const int r  = i >> 5;
        const int c4 = (i & 31) * 4;
        const float4 v = *(const float4*)&W[(size_t)(o0 + r) * (2 * D) + woff + c4];
        w[r][c4 + 0] = v.x; w[r][c4 + 1] = v.y;
        w[r][c4 + 2] = v.z; w[r][c4 + 3] = v.w;
    }

    // build the 128-component vector (one component per thread, coalesced)
    if (is_const) {
        const int s = g * idx;
        float sum = 0.f;
        #pragma unroll 16
        for (int a = 0; a < A; a++) {
            int r = s + a; if (r >= N) r -= N;
            sum += embeds[(size_t)r * D + tid];
        }
        ev[tid] = sum;
    } else {
        const int row = anchor[idx - T];
        ev[tid] = embeds[(size_t)row * D + tid];
    }
    __syncthreads();

    // per-thread dot, k split in halves across the two warps-pairs
    const int o = tid & 63;
    const int h = tid >> 6;
    float acc = 0.f;
    #pragma unroll
    for (int k = 0; k < 64; k++)
        acc += ev[64 * h + k] * w[o][64 * h + k];   // (o + k) % 32 -> conflict-free

    if (h) part[o] = acc;
    __syncthreads();
    if (!h) {
        const float tot = (acc + part[o]) * (1.0f / A);
        if (is_const) g_C[(size_t)idx * D + o0 + o] = tot + b[o0 + o];
        else          g_V[(idx - T) * D + o0 + o]   = tot;
    }
}

// ---------------------------------------------------------------------------
// k_main: out[n][o] = sum_a sd[a][n] * sv[a][o]  +  C[(step*n) mod T][o]
// 256 threads, tile 64 n x 128 o; each thread 8n x 4o via packed f32x2 FMA
// (accumulators hold n-pairs: acc2[i][j] = (n=2i, n=2i+1) for o = ob+j).
// ---------------------------------------------------------------------------
__global__ __launch_bounds__(256) void k_main(const float* __restrict__ dists,
                                              float* __restrict__ out,
                                              int N, int T, int step) {
    __shared__ float sv[A][D];    // 32768 B
    __shared__ float sd[A][TN];   // 16384 B

    const int n0  = blockIdx.x * TN;
    const int tid = threadIdx.x;

    // stage V
    #pragma unroll
    for (int i = tid; i < A * D / 4; i += 256)
        ((float4*)sv)[i] = ((const float4*)g_V)[i];

    // stage dists tile (zero-padded at the tail)
    #pragma unroll
    for (int i = tid; i < A * TN / 4; i += 256) {
        const int a  = i / (TN / 4);
        const int j4 = (i % (TN / 4)) * 4;
        const int n  = n0 + j4;
        const float* src = dists + (size_t)a * N + n;
        float4 v;
        if (n + 3 < N) {
            v = *(const float4*)src;
        } else {
            v.x = (n + 0 < N) ? src[0] : 0.f;
            v.y = (n + 1 < N) ? src[1] : 0.f;
            v.z = (n + 2 < N) ? src[2] : 0.f;
            v.w = (n + 3 < N) ? src[3] : 0.f;
        }
        ((float4*)sd)[i] = v;
    }
    __syncthreads();

    const int ob = (tid & 31) * 4;   // o base (lanes cover all 128 o)
    const int nb = (tid >> 5) * 8;   // n base (per-warp constant, smem broadcast)

    unsigned long long acc2[4][4];
    #pragma unroll
    for (int i = 0; i < 4; i++)
        #pragma unroll
        for (int j = 0; j < 4; j++) acc2[i][j] = 0ull;

    #pragma unroll 8
    for (int a = 0; a < A; a++) {
        const float4 v  = *(const float4*)&sv[a][ob];
        const float4 d0 = *(const float4*)&sd[a][nb];
        const float4 d1 = *(const float4*)&sd[a][nb + 4];

        unsigned long long vv[4];
        vv[0] = pk2(v.x, v.x); vv[1] = pk2(v.y, v.y);
        vv[2] = pk2(v.z, v.z); vv[3] = pk2(v.w, v.w);

        unsigned long long dp[4];      // adjacent-register packs (near-free)
        dp[0] = pk2(d0.x, d0.y); dp[1] = pk2(d0.z, d0.w);
        dp[2] = pk2(d1.x, d1.y); dp[3] = pk2(d1.z, d1.w);

        #pragma unroll
        for (int i = 0; i < 4; i++)
            #pragma unroll
            for (int j = 0; j < 4; j++)
                ffma2(acc2[i][j], dp[i], vv[j]);
    }

    // epilogue: unpack, add C[t(n)], store
    #pragma unroll
    for (int i = 0; i < 4; i++) {
        float r0[4], r1[4];
        #pragma unroll
        for (int j = 0; j < 4; j++) unpk2(acc2[i][j], r0[j], r1[j]);

        #pragma unroll
        for (int p = 0; p < 2; p++) {
            const int n = n0 + nb + 2 * i + p;
            if (n < N) {
                const int t = (int)(((long long)step * n) % T);
                const float4 c = *(const float4*)&g_C[(size_t)t * D + ob];
                const float* rr = p ? r1 : r0;
                float4 r;
                r.x = rr[0] + c.x; r.y = rr[1] + c.y;
                r.z = rr[2] + c.z; r.w = rr[3] + c.w;
                *(float4*)&out[(size_t)n * D + ob] = r;
            }
        }
    }
}

// ---------------------------------------------------------------------------
extern "C" void kernel_launch(void* const* d_in, const int* in_sizes, int n_in,
                              void* d_out, int out_size) {
    const float* embeds = (const float*)d_in[0];   // [N, 128]
    const float* dists  = (const float*)d_in[1];   // [64, N]
    const float* W      = (const float*)d_in[2];   // [128, 256]
    const float* b      = (const float*)d_in[3];   // [128]
    const int*   anchor = (const int*)  d_in[4];   // [64] int32
    float* out = (float*)d_out;

    const int N = in_sizes[0] / D;                 // 10000

    // g = gcd(A, N); T = N/g distinct windows; t(n) = (A/g * n) mod T
    int g = A, y = N;
    while (y) { int r = g % y; g = y; y = r; }
    const int T    = N / g;
    const int step = A / g;

    k_pre<<<2 * (T + A), 128>>>(embeds, W, b, anchor, N, T, g);
    k_main<<<(N + TN - 1) / TN, 256>>>(dists, out, N, T, step);
}